// round 11
// baseline (speedup 1.0000x reference)
#include <cuda_runtime.h>
#include <math.h>

// Allpass biquad over [B, 1, T] fp32, T = 480000.
// R11: warp-autonomous pipelines. Each WARP owns 1024-sample chunks
// (32 segments x 32 samples/lane, 16-sample warm-up; poles decay
// 0.414/sample -> truncation ~7.5e-7), with its own double-buffered smem
// stage, its own cp.async groups, and its own dynamic work grabs.
// Zero __syncthreads: every cross-lane dependency is warp-local
// (lane-0 warm-up comes from a gmem-prefetched tail slot), so the 8 warps
// of a block never couple and DRAM traffic stays smooth.

#define T_LEN    480000
#define SEG      32
#define WCHUNK   (SEG * 32)          // 1024 samples per warp-chunk
#define WCH_PER_ROW 469              // 468 full + tail of 768
#define WARM     16
#define SSTRIDE  (SEG + 4)           // 36: conflict-free LDS.128 phases
#define WREGION  (32 * SSTRIDE)      // 1152 floats
#define TAILOFF  WREGION             // 16-float prev-tail slot
#define WSTAGE   1184                // padded stage (floats, 16B aligned)
#define NTHREADS 256
#define NWARPS   (NTHREADS / 32)
#define GRID_BLOCKS 444              // 148 SMs * 3 blocks
#define TOTAL_WARPS (GRID_BLOCKS * NWARPS)   // 3552
#define FULL 0xffffffffu

// work counter starts past the statically-assigned first warp-chunks; the
// last finishing warp restores it for the next launch (graph replay safe).
__device__ unsigned int g_chunk_ctr = TOTAL_WARPS;
__device__ unsigned int g_done_ctr  = 0;

__device__ __forceinline__ void cp_async16(float* dst_smem, const float* src) {
    unsigned d = (unsigned)__cvta_generic_to_shared(dst_smem);
    asm volatile("cp.async.cg.shared.global [%0], [%1], 16;\n"
                 :: "r"(d), "l"(src) : "memory");
}

__global__ void __launch_bounds__(NTHREADS, 3)
allpass_kernel(const float* __restrict__ x, float* __restrict__ y,
               float b0, float b1, float b2, float a1, float a2,
               int total_wch)
{
    extern __shared__ float sm[];    // NWARPS * 2 * WSTAGE
    const int warp = threadIdx.x >> 5;
    const int lane = threadIdx.x & 31;
    float* wbase = sm + warp * 2 * WSTAGE;

    // issue cp.async copies for warp-chunk idx into stage sb (warp-local)
    auto issue = [&](int idx, float* sb) {
        const int row  = idx / WCH_PER_ROW;
        const int ch   = idx % WCH_PER_ROW;
        const float* xr = x + (size_t)row * T_LEN;
        const int base = ch * WCHUNK;
        const int clen = min(WCHUNK, T_LEN - base);   // 1024 or 768
        #pragma unroll
        for (int r = 0; r < 8; r++) {
            const int j = (r * 32 + lane) * 4;
            if (j < clen) {
                const int seg = j >> 5;
                const int k   = j & 31;
                cp_async16(&sb[seg * SSTRIDE + k], xr + base + j);
            }
        }
        if (ch > 0 && lane < 4)   // prev 16 samples (lane 0's warm-up)
            cp_async16(&sb[TAILOFF + lane * 4], xr + base - WARM + lane * 4);
    };

    // first chunk static; grab the next one immediately (latency hidden)
    int my = blockIdx.x * NWARPS + warp;
    unsigned nxt_l = 0;
    if (lane == 0) nxt_l = atomicAdd(&g_chunk_ctr, 1u);
    if (my < total_wch) issue(my, wbase);
    asm volatile("cp.async.commit_group;\n" ::: "memory");
    int nxt = (int)__shfl_sync(FULL, nxt_l, 0);

    int buf = 0;
    while (my < total_wch) {
        // prefetch next chunk into the other buffer
        const int nn = nxt;
        if (nn < total_wch) issue(nn, wbase + (buf ^ 1) * WSTAGE);
        asm volatile("cp.async.commit_group;\n" ::: "memory");
        // grab the following index now; result consumed after compute
        if (lane == 0) nxt_l = atomicAdd(&g_chunk_ctr, 1u);
        asm volatile("cp.async.wait_group 1;\n" ::: "memory");
        __syncwarp();

        const int row  = my / WCH_PER_ROW;
        const int ch   = my % WCH_PER_ROW;
        const int base = ch * WCHUNK;
        const int clen = min(WCHUNK, T_LEN - base);
        const int n_seg = clen >> 5;                  // 32 or 24
        float* sb = wbase + buf * WSTAGE;
        float* yr = y + (size_t)row * T_LEN;

        // ---- warm-up: 16 serial samples, vectorized loads ----
        float y1 = 0.0f, y2 = 0.0f, x1 = 0.0f, x2 = 0.0f;
        if (lane < n_seg && (lane > 0 || ch > 0)) {
            const float* w = (lane > 0)
                ? &sb[(lane - 1) * SSTRIDE + (SEG - WARM)]
                : &sb[TAILOFF];
            float wv[WARM];
            #pragma unroll
            for (int q = 0; q < WARM / 4; q++)
                *reinterpret_cast<float4*>(&wv[q * 4]) =
                    *reinterpret_cast<const float4*>(w + q * 4);
            #pragma unroll
            for (int k = 0; k < WARM; k++) {
                const float xv = wv[k];
                const float yn = b0 * xv + b1 * x1 + b2 * x2
                               - a1 * y1 - a2 * y2;
                y2 = y1; y1 = yn; x2 = x1; x1 = xv;
            }
        }
        __syncwarp();   // neighbor-tail reads before in-place overwrite

        // ---- recurrence: 32 samples, LDS.128 / STS.128 in place ----
        if (lane < n_seg) {
            float* s = &sb[lane * SSTRIDE];
            #pragma unroll
            for (int k4 = 0; k4 < SEG / 4; k4++) {
                float4 v = *reinterpret_cast<float4*>(s + k4 * 4);
                float yn;
                yn = b0 * v.x + b1 * x1 + b2 * x2 - a1 * y1 - a2 * y2;
                y2 = y1; y1 = yn; x2 = x1; x1 = v.x; v.x = yn;
                yn = b0 * v.y + b1 * x1 + b2 * x2 - a1 * y1 - a2 * y2;
                y2 = y1; y1 = yn; x2 = x1; x1 = v.y; v.y = yn;
                yn = b0 * v.z + b1 * x1 + b2 * x2 - a1 * y1 - a2 * y2;
                y2 = y1; y1 = yn; x2 = x1; x1 = v.z; v.z = yn;
                yn = b0 * v.w + b1 * x1 + b2 * x2 - a1 * y1 - a2 * y2;
                y2 = y1; y1 = yn; x2 = x1; x1 = v.w; v.w = yn;
                *reinterpret_cast<float4*>(s + k4 * 4) = v;
            }
        }
        __syncwarp();

        // ---- gather-out: LDS.128 -> coalesced streaming STG.128 ----
        #pragma unroll
        for (int r = 0; r < 8; r++) {
            const int j = (r * 32 + lane) * 4;
            if (j < clen) {
                const int seg = j >> 5;
                const int k   = j & 31;
                const float4 v =
                    *reinterpret_cast<const float4*>(&sb[seg * SSTRIDE + k]);
                __stcs(reinterpret_cast<float4*>(yr + base + j), v);
            }
        }
        __syncwarp();   // buffer reused by the prefetch next iteration

        my = nn;
        nxt = (int)__shfl_sync(FULL, nxt_l, 0);
        buf ^= 1;
    }

    // ---- self-reset: last finishing warp restores the counter.
    // Every warp's final grab precedes its done-increment (fence-ordered),
    // so when g_done_ctr hits TOTAL_WARPS no grabs remain in flight.
    if (lane == 0) {
        __threadfence();
        const unsigned d = atomicAdd(&g_done_ctr, 1u);
        if (d == TOTAL_WARPS - 1) {
            g_chunk_ctr = TOTAL_WARPS;
            __threadfence();
            atomicExch(&g_done_ctr, 0u);
        }
    }
}

extern "C" void kernel_launch(void* const* d_in, const int* in_sizes, int n_in,
                              void* d_out, int out_size)
{
    const float* x = (const float*)d_in[0];
    float* y = (float*)d_out;

    const int total = in_sizes[0];
    const int B = total / T_LEN;   // 64

    // Coefficients in float64 then cast, matching the numpy reference.
    const double w0    = 2.0 * M_PI * 4000.0 / 16000.0;
    const double alpha = sin(w0) / (2.0 * 0.707);
    const double cw0   = cos(w0);
    const double a0d   = 1.0 + alpha;
    const float b0 = (float)((1.0 - alpha) / a0d);
    const float b1 = (float)((-2.0 * cw0) / a0d);
    const float b2 = (float)((1.0 + alpha) / a0d);
    const float a1 = (float)((-2.0 * cw0) / a0d);
    const float a2 = (float)((1.0 - alpha) / a0d);

    const int smem_bytes = NWARPS * 2 * WSTAGE * (int)sizeof(float); // ~74 KB
    static bool attr_set = false;
    if (!attr_set) {
        cudaFuncSetAttribute(allpass_kernel,
                             cudaFuncAttributeMaxDynamicSharedMemorySize,
                             smem_bytes);
        attr_set = true;
    }

    const int total_wch = B * WCH_PER_ROW;   // 30016

    allpass_kernel<<<GRID_BLOCKS, NTHREADS, smem_bytes>>>(
        x, y, b0, b1, b2, a1, a2, total_wch);
}

// round 12
// speedup vs baseline: 1.1338x; 1.1338x over previous
#include <cuda_runtime.h>
#include <cuda.h>
#include <math.h>
#include <stdint.h>

// Allpass biquad over [B, 1, T] fp32, T = 480000.
// R12: TMA bulk-tensor pipeline. Each 8192-sample chunk is ONE 3D TMA load
// (box [32 floats, 256 segs, 1 row], SW128) + ONE TMA store; the LSU only
// does the in-smem recurrence (thread-serial 32-sample segments, 16-sample
// warm-up; poles decay 0.414/sample -> truncation ~7.5e-7). Triple-buffered
// stages, persistent blocks, dynamic scheduling, self-resetting counter.

#define T_LEN        480000
#define SEG          32
#define NSEG_CHUNK   256
#define CHUNK        (SEG * NSEG_CHUNK)     // 8192 samples
#define SEGS_PER_ROW (T_LEN / SEG)          // 15000
#define CHUNKS_PER_ROW 59                   // ceil(15000/256)
#define WARM         16
#define NTHREADS     256
#define GRID_BLOCKS  296                    // 148 SMs * 2 blocks
#define NSTAGE       3
#define STAGE_BYTES  (33 * 1024)            // 32KB main + 128B tail + pad
#define TAIL_OFF_B   32768                  // 1024-aligned tail slot
#define CTRL_OFF_B   (NSTAGE * STAGE_BYTES) // 101376
#define SMEM_BYTES   (CTRL_OFF_B + 64)
#define EXPECT_BYTES (32768u + 128u)

__device__ unsigned int g_chunk_ctr = GRID_BLOCKS;
__device__ unsigned int g_done_ctr  = 0;

__device__ __forceinline__ uint32_t smem_u32(const void* p) {
    return (uint32_t)__cvta_generic_to_shared(p);
}

__global__ void __launch_bounds__(NTHREADS, 2)
allpass_kernel(const __grid_constant__ CUtensorMap mx,
               const __grid_constant__ CUtensorMap mtail,
               const __grid_constant__ CUtensorMap my_map,
               float b0, float b1, float b2, float a1, float a2,
               int total_chunks)
{
    extern __shared__ unsigned char smem[];
    const int tid = threadIdx.x;
    const uint32_t mbar0 = smem_u32(smem + CTRL_OFF_B);
    int* s_next = (int*)(smem + CTRL_OFF_B + 32);

    if (tid == 0) {
        asm volatile("prefetch.tensormap [%0];" :: "l"((const void*)&mx));
        asm volatile("prefetch.tensormap [%0];" :: "l"((const void*)&mtail));
        asm volatile("prefetch.tensormap [%0];" :: "l"((const void*)&my_map));
        #pragma unroll
        for (int s = 0; s < NSTAGE; s++)
            asm volatile("mbarrier.init.shared.b64 [%0], 1;"
                         :: "r"(mbar0 + s * 8) : "memory");
    }
    __syncthreads();

    // tid0 only: one expect_tx + main box load + 32-float history load.
    // Negative / past-end segment coords are zero-filled by TMA, which
    // exactly models the zero initial state at t<0.
    auto issue_load = [&](int idx, int s) {
        const int row  = idx / CHUNKS_PER_ROW;
        const int ch   = idx % CHUNKS_PER_ROW;
        const int seg0 = ch * NSEG_CHUNK;
        const uint32_t mb = mbar0 + s * 8;
        asm volatile("mbarrier.arrive.expect_tx.shared.b64 _, [%0], %1;"
                     :: "r"(mb), "r"(EXPECT_BYTES) : "memory");
        const uint32_t dst = smem_u32(smem + s * STAGE_BYTES);
        asm volatile(
            "cp.async.bulk.tensor.3d.shared::cta.global.tile"
            ".mbarrier::complete_tx::bytes [%0], [%1, {%2, %3, %4}], [%5];"
            :: "r"(dst), "l"((const void*)&mx),
               "r"(0), "r"(seg0), "r"(row), "r"(mb) : "memory");
        const uint32_t dstt = smem_u32(smem + s * STAGE_BYTES + TAIL_OFF_B);
        asm volatile(
            "cp.async.bulk.tensor.3d.shared::cta.global.tile"
            ".mbarrier::complete_tx::bytes [%0], [%1, {%2, %3, %4}], [%5];"
            :: "r"(dstt), "l"((const void*)&mtail),
               "r"(0), "r"(seg0 - 1), "r"(row), "r"(mb) : "memory");
    };

    int my = blockIdx.x;
    if (tid == 0 && my < total_chunks) issue_load(my, 0);

    unsigned ph0 = 0, ph1 = 0, ph2 = 0;
    int it = 0;
    while (my < total_chunks) {
        if (tid == 0) *s_next = (int)atomicAdd(&g_chunk_ctr, 1u);
        __syncthreads();
        const int nidx = *s_next;
        const int cs = it % NSTAGE;
        const int ns = (it + 1) % NSTAGE;

        if (tid == 0) {
            // stage ns was stored 2 iterations ago; allow only the most
            // recent store group to still be pending before overwriting.
            asm volatile("cp.async.bulk.wait_group 1;" ::: "memory");
            if (nidx < total_chunks) issue_load(nidx, ns);
        }

        // wait for the current stage's TMA load
        {
            const uint32_t mb = mbar0 + cs * 8;
            const unsigned par = (cs == 0) ? ph0 : ((cs == 1) ? ph1 : ph2);
            asm volatile(
                "{\n\t.reg .pred P;\n"
                "WAIT_%=:\n\t"
                "mbarrier.try_wait.parity.acquire.cta.shared::cta.b64 "
                "P, [%0], %1, 0x989680;\n\t"
                "@P bra DONE_%=;\n\t"
                "bra WAIT_%=;\n"
                "DONE_%=:\n\t}"
                :: "r"(mb), "r"(par) : "memory");
        }
        if (cs == 0) ph0 ^= 1; else if (cs == 1) ph1 ^= 1; else ph2 ^= 1;

        const int row  = my / CHUNKS_PER_ROW;
        const int ch   = my % CHUNKS_PER_ROW;
        const int seg0 = ch * NSEG_CHUNK;
        const int n_seg = min(NSEG_CHUNK, SEGS_PER_ROW - seg0);
        float* sb = (float*)(smem + cs * STAGE_BYTES);

        if (tid < n_seg) {
            // ---- warm-up: 16 samples from the previous segment's tail ----
            float y1 = 0.0f, y2 = 0.0f, x1 = 0.0f, x2 = 0.0f;
            {
                float wv[WARM];
                if (tid > 0) {
                    const int r = tid - 1;
                    #pragma unroll
                    for (int q = 0; q < WARM / 4; q++) {
                        const int boff = (64 + q * 16) ^ ((r & 7) * 16);
                        *reinterpret_cast<float4*>(&wv[q * 4]) =
                            *reinterpret_cast<const float4*>(
                                (const char*)sb + r * 128 + boff);
                    }
                } else {
                    const float* tl = (const float*)((const char*)sb + TAIL_OFF_B);
                    #pragma unroll
                    for (int q = 0; q < WARM / 4; q++)
                        *reinterpret_cast<float4*>(&wv[q * 4]) =
                            *reinterpret_cast<const float4*>(tl + WARM + q * 4);
                }
                #pragma unroll
                for (int k = 0; k < WARM; k++) {
                    const float xv = wv[k];
                    const float yn = b0 * xv + b1 * x1 + b2 * x2
                                   - a1 * y1 - a2 * y2;
                    y2 = y1; y1 = yn; x2 = x1; x1 = xv;
                }
            }
            // ---- recurrence: 32 samples in place (SW128-aware) ----
            char* srow = (char*)sb + tid * 128;
            const int sw = (tid & 7) * 16;
            #pragma unroll
            for (int c = 0; c < 8; c++) {
                float4* p = reinterpret_cast<float4*>(srow + ((c * 16) ^ sw));
                float4 v = *p;
                float yn;
                yn = b0 * v.x + b1 * x1 + b2 * x2 - a1 * y1 - a2 * y2;
                y2 = y1; y1 = yn; x2 = x1; x1 = v.x; v.x = yn;
                yn = b0 * v.y + b1 * x1 + b2 * x2 - a1 * y1 - a2 * y2;
                y2 = y1; y1 = yn; x2 = x1; x1 = v.y; v.y = yn;
                yn = b0 * v.z + b1 * x1 + b2 * x2 - a1 * y1 - a2 * y2;
                y2 = y1; y1 = yn; x2 = x1; x1 = v.z; v.z = yn;
                yn = b0 * v.w + b1 * x1 + b2 * x2 - a1 * y1 - a2 * y2;
                y2 = y1; y1 = yn; x2 = x1; x1 = v.w; v.w = yn;
                *p = v;
            }
        }
        __syncthreads();

        // ---- TMA store (clips OOB rows on the tail chunk) ----
        if (tid == 0) {
            asm volatile("fence.proxy.async.shared::cta;" ::: "memory");
            const uint32_t src = smem_u32(smem + cs * STAGE_BYTES);
            asm volatile(
                "cp.async.bulk.tensor.3d.global.shared::cta.tile.bulk_group "
                "[%0, {%1, %2, %3}], [%4];"
                :: "l"((const void*)&my_map),
                   "r"(0), "r"(seg0), "r"(row), "r"(src) : "memory");
            asm volatile("cp.async.bulk.commit_group;" ::: "memory");
        }

        my = nidx;
        it++;
    }

    // drain outstanding TMA stores before the CTA (and its smem) retires
    if (tid == 0)
        asm volatile("cp.async.bulk.wait_group 0;" ::: "memory");

    // self-reset for the next launch: last finishing block restores counter
    if (tid == 0) {
        __threadfence();
        const unsigned d = atomicAdd(&g_done_ctr, 1u);
        if (d == gridDim.x - 1) {
            g_chunk_ctr = gridDim.x;
            __threadfence();
            atomicExch(&g_done_ctr, 0u);
        }
    }
}

typedef CUresult (*EncFn)(CUtensorMap*, CUtensorMapDataType, cuuint32_t, void*,
                          const cuuint64_t*, const cuuint64_t*,
                          const cuuint32_t*, const cuuint32_t*,
                          CUtensorMapInterleave, CUtensorMapSwizzle,
                          CUtensorMapL2promotion, CUtensorMapFloatOOBfill);

extern "C" void kernel_launch(void* const* d_in, const int* in_sizes, int n_in,
                              void* d_out, int out_size)
{
    const float* x = (const float*)d_in[0];
    float* y = (float*)d_out;

    const int total = in_sizes[0];
    const int B = total / T_LEN;   // 64

    // Coefficients in float64 then cast, matching the numpy reference.
    const double w0    = 2.0 * M_PI * 4000.0 / 16000.0;
    const double alpha = sin(w0) / (2.0 * 0.707);
    const double cw0   = cos(w0);
    const double a0d   = 1.0 + alpha;
    const float b0 = (float)((1.0 - alpha) / a0d);
    const float b1 = (float)((-2.0 * cw0) / a0d);
    const float b2 = (float)((1.0 + alpha) / a0d);
    const float a1 = (float)((-2.0 * cw0) / a0d);
    const float a2 = (float)((1.0 - alpha) / a0d);

    // tensor-map encoder via driver entry point (no -lcuda needed)
    EncFn enc = nullptr;
    {
        void* p = nullptr;
        cudaDriverEntryPointQueryResult st;
        cudaGetDriverEntryPointByVersion("cuTensorMapEncodeTiled", &p, 12000,
                                         cudaEnableDefault, &st);
        enc = (EncFn)p;
    }

    // x/y viewed as [32 floats][15000 segs][B rows]
    cuuint64_t dims[3]    = {32, (cuuint64_t)SEGS_PER_ROW, (cuuint64_t)B};
    cuuint64_t strides[2] = {SEG * 4, (cuuint64_t)T_LEN * 4};
    cuuint32_t box_main[3] = {32, NSEG_CHUNK, 1};
    cuuint32_t box_tail[3] = {32, 1, 1};
    cuuint32_t estr[3]     = {1, 1, 1};

    CUtensorMap mx, mtail, my_map;
    enc(&mx, CU_TENSOR_MAP_DATA_TYPE_FLOAT32, 3, (void*)x, dims, strides,
        box_main, estr, CU_TENSOR_MAP_INTERLEAVE_NONE,
        CU_TENSOR_MAP_SWIZZLE_128B, CU_TENSOR_MAP_L2_PROMOTION_L2_128B,
        CU_TENSOR_MAP_FLOAT_OOB_FILL_NONE);
    enc(&mtail, CU_TENSOR_MAP_DATA_TYPE_FLOAT32, 3, (void*)x, dims, strides,
        box_tail, estr, CU_TENSOR_MAP_INTERLEAVE_NONE,
        CU_TENSOR_MAP_SWIZZLE_NONE, CU_TENSOR_MAP_L2_PROMOTION_L2_128B,
        CU_TENSOR_MAP_FLOAT_OOB_FILL_NONE);
    enc(&my_map, CU_TENSOR_MAP_DATA_TYPE_FLOAT32, 3, (void*)y, dims, strides,
        box_main, estr, CU_TENSOR_MAP_INTERLEAVE_NONE,
        CU_TENSOR_MAP_SWIZZLE_128B, CU_TENSOR_MAP_L2_PROMOTION_L2_128B,
        CU_TENSOR_MAP_FLOAT_OOB_FILL_NONE);

    static bool attr_set = false;
    if (!attr_set) {
        cudaFuncSetAttribute(allpass_kernel,
                             cudaFuncAttributeMaxDynamicSharedMemorySize,
                             SMEM_BYTES);
        attr_set = true;
    }

    const int total_chunks = B * CHUNKS_PER_ROW;   // 3776

    allpass_kernel<<<GRID_BLOCKS, NTHREADS, SMEM_BYTES>>>(
        mx, mtail, my_map, b0, b1, b2, a1, a2, total_chunks);
}